// round 8
// baseline (speedup 1.0000x reference)
#include <cuda_runtime.h>
#include <cstdint>

// PercolationQ: per-patch occupancy fraction -> threshold -> mean over patches.
// Pure HBM-bound streaming reduction over three 50 MB fp32 tensors.
//
//   x4 : [3,64,4096,4,4]   patch = 16 floats
//   x8 : [3,64,1024,8,8]   patch = 64 floats
//   x16: [3,64, 256,16,16] patch = 256 floats
// Output: [q4(3,64), q8(3,64), q16(3,64)] = 576 floats.
//
// R7: TMA-style async bulk pipeline. Each block owns one 64 KB chunk and
// streams it through a 3-stage x 8 KB smem ring via cp.async.bulk + mbarrier
// (producer = elected thread, consumers = 8 warps, 1 KB slice each).
// The async copy engine keeps 24 KB of HBM requests in flight per block
// independent of warp scheduling -- removing the LDG demand gaps that capped
// R4-R6 at ~5.4 TB/s. Last block finalizes in-kernel (ticket pattern).

#define PERC_THR 0.59275f
#define NCHUNK 2304
#define NSTAGE 3
#define STG_BYTES 8192
#define NSTG_CHUNK 8           // 8 x 8KB = 64KB per chunk

__device__ int g_part[NCHUNK];          // per-chunk patch counts
__device__ unsigned int g_ticket = 0;   // self-resetting -> deterministic replays

// ---------- PTX helpers ----------
__device__ __forceinline__ uint32_t smem_u32(const void* p) {
    uint32_t a;
    asm("{ .reg .u64 t; cvta.to.shared.u64 t, %1; cvt.u32.u64 %0, t; }"
        : "=r"(a) : "l"(p));
    return a;
}
__device__ __forceinline__ void mbar_init(uint32_t mbar, uint32_t count) {
    asm volatile("mbarrier.init.shared.b64 [%0], %1;" :: "r"(mbar), "r"(count) : "memory");
}
__device__ __forceinline__ void mbar_expect_tx(uint32_t mbar, uint32_t bytes) {
    asm volatile("mbarrier.arrive.expect_tx.shared.b64 _, [%0], %1;"
                 :: "r"(mbar), "r"(bytes) : "memory");
}
__device__ __forceinline__ void mbar_arrive(uint32_t mbar) {
    asm volatile("mbarrier.arrive.shared.b64 _, [%0];" :: "r"(mbar) : "memory");
}
__device__ __forceinline__ void mbar_wait(uint32_t mbar, uint32_t parity) {
    asm volatile(
        "{\n\t.reg .pred P;\n\t"
        "W_%=:\n\t"
        "mbarrier.try_wait.parity.acquire.cta.shared::cta.b64 P, [%0], %1, 0x989680;\n\t"
        "@P bra.uni D_%=;\n\t"
        "bra.uni W_%=;\n\t"
        "D_%=:\n\t}"
        :: "r"(mbar), "r"(parity) : "memory");
}
__device__ __forceinline__ void bulk_g2s(uint32_t dst_smem, const void* src,
                                         uint32_t bytes, uint32_t mbar) {
    asm volatile(
        "cp.async.bulk.shared::cta.global.mbarrier::complete_tx::bytes "
        "[%0], [%1], %2, [%3];"
        :: "r"(dst_smem), "l"(src), "r"(bytes), "r"(mbar) : "memory");
}
// ---------------------------------

__device__ __forceinline__ float red4(float4 a) {
    return (a.x + a.y) + (a.z + a.w);
}

// Returns valid total only on threadIdx.x == 0.
__device__ __forceinline__ int block_reduce_count(int c, int* sh) {
    c = __reduce_add_sync(0xffffffffu, c);
    int warp = threadIdx.x >> 5;
    if ((threadIdx.x & 31) == 0) sh[warp] = c;
    __syncthreads();
    if (threadIdx.x == 0) {
        int s = 0;
#pragma unroll
        for (int i = 0; i < 8; i++) s += sh[i];
        return s;
    }
    return 0;
}

__global__ void __launch_bounds__(256)
perc_kernel(const float* __restrict__ x4,
            const float* __restrict__ x8,
            const float* __restrict__ x16,
            float* __restrict__ out) {
    __shared__ __align__(128) unsigned char buf[NSTAGE][STG_BYTES];
    __shared__ __align__(8) unsigned long long mb_full_s[NSTAGE];
    __shared__ __align__(8) unsigned long long mb_empty_s[NSTAGE];
    __shared__ int sh[8];
    __shared__ bool sh_last;

    const int tid  = threadIdx.x;
    const int warp = tid >> 5;
    const int lane = tid & 31;
    const int chunk = blockIdx.x;

    // Which tensor does this chunk belong to?
    const char* src;
    int tcase;
    if (chunk < 768)       { src = (const char*)x4  + (size_t)chunk * 65536;          tcase = 0; }
    else if (chunk < 1536) { src = (const char*)x8  + (size_t)(chunk - 768) * 65536;  tcase = 1; }
    else                   { src = (const char*)x16 + (size_t)(chunk - 1536) * 65536; tcase = 2; }

    uint32_t full_a[NSTAGE], empty_a[NSTAGE], buf_a[NSTAGE];
#pragma unroll
    for (int s = 0; s < NSTAGE; s++) {
        full_a[s]  = smem_u32(&mb_full_s[s]);
        empty_a[s] = smem_u32(&mb_empty_s[s]);
        buf_a[s]   = smem_u32(buf[s]);
    }

    if (tid == 0) {
#pragma unroll
        for (int s = 0; s < NSTAGE; s++) {
            mbar_init(full_a[s], 1);    // producer's expect_tx + tx completes it
            mbar_init(empty_a[s], 8);   // one arrive per warp
        }
        // make inits visible to the async proxy before TMA targets them
        asm volatile("fence.proxy.async.shared::cta;" ::: "memory");
    }
    __syncthreads();

    // Prologue: fill the pipeline (3 stages in flight)
    if (tid == 0) {
#pragma unroll
        for (int s = 0; s < NSTAGE; s++) {
            mbar_expect_tx(full_a[s], STG_BYTES);
            bulk_g2s(buf_a[s], src + (size_t)s * STG_BYTES, STG_BYTES, full_a[s]);
        }
    }

    int cnt = 0;
    int bufi = 0, phase = 0;   // rolling stage index + parity ((s/NSTAGE)&1)
#pragma unroll 1
    for (int s = 0; s < NSTG_CHUNK; s++) {
        // ---- consume stage s from buf[bufi] ----
        mbar_wait(full_a[bufi], phase);

        // warp slice = 1 KB = 64 float4 -> 2 warp-iterations
        const float4* slice = (const float4*)(buf[bufi] + warp * 1024);
        float4 v0 = slice[lane];
        float4 v1 = slice[32 + lane];

        if (tcase == 0) {
            // x4: 4-lane patches
            float a = red4(v0);
            a += __shfl_xor_sync(0xffffffffu, a, 1);
            a += __shfl_xor_sync(0xffffffffu, a, 2);
            float b = red4(v1);
            b += __shfl_xor_sync(0xffffffffu, b, 1);
            b += __shfl_xor_sync(0xffffffffu, b, 2);
            if ((lane & 3) == 0) {
                cnt += (a * 0.0625f >= PERC_THR) ? 1 : 0;
                cnt += (b * 0.0625f >= PERC_THR) ? 1 : 0;
            }
        } else if (tcase == 1) {
            // x8: 16-lane patches
            float a = red4(v0);
            a += __shfl_xor_sync(0xffffffffu, a, 1);
            a += __shfl_xor_sync(0xffffffffu, a, 2);
            a += __shfl_xor_sync(0xffffffffu, a, 4);
            a += __shfl_xor_sync(0xffffffffu, a, 8);
            float b = red4(v1);
            b += __shfl_xor_sync(0xffffffffu, b, 1);
            b += __shfl_xor_sync(0xffffffffu, b, 2);
            b += __shfl_xor_sync(0xffffffffu, b, 4);
            b += __shfl_xor_sync(0xffffffffu, b, 8);
            if ((lane & 15) == 0) {
                cnt += (a * 0.015625f >= PERC_THR) ? 1 : 0;
                cnt += (b * 0.015625f >= PERC_THR) ? 1 : 0;
            }
        } else {
            // x16: the whole 1 KB slice is exactly one 256-float patch
            float a = red4(v0) + red4(v1);
            a += __shfl_xor_sync(0xffffffffu, a, 1);
            a += __shfl_xor_sync(0xffffffffu, a, 2);
            a += __shfl_xor_sync(0xffffffffu, a, 4);
            a += __shfl_xor_sync(0xffffffffu, a, 8);
            a += __shfl_xor_sync(0xffffffffu, a, 16);
            if (lane == 0)
                cnt += (a * 0.00390625f >= PERC_THR) ? 1 : 0;
        }

        __syncwarp();
        if (lane == 0) mbar_arrive(empty_a[bufi]);

        // ---- producer: refill this stage for s+NSTAGE ----
        if (tid == 0 && s + NSTAGE < NSTG_CHUNK) {
            mbar_wait(empty_a[bufi], phase);   // all 8 warps consumed stage s
            mbar_expect_tx(full_a[bufi], STG_BYTES);
            bulk_g2s(buf_a[bufi], src + (size_t)(s + NSTAGE) * STG_BYTES,
                     STG_BYTES, full_a[bufi]);
        }

        if (++bufi == NSTAGE) { bufi = 0; phase ^= 1; }
    }

    int total = block_reduce_count(cnt, sh);
    if (tid == 0) g_part[chunk] = total;

    // ---- last-block finalize (threadfence-reduction pattern) ----
    if (tid == 0) {
        __threadfence();                       // publish g_part writes
        unsigned int t = atomicAdd(&g_ticket, 1);
        sh_last = (t == gridDim.x - 1);
    }
    __syncthreads();
    if (sh_last) {
        for (int t = tid; t < 576; t += 256) {
            const int tensor = t / 192;        // 0: x4, 1: x8, 2: x16
            const int row = t % 192;
            const int* part = g_part + tensor * 768 + row * 4;
            int c = part[0] + part[1] + part[2] + part[3];
            const float invP = (tensor == 0) ? (1.0f / 4096.0f)
                             : (tensor == 1) ? (1.0f / 1024.0f)
                                             : (1.0f / 256.0f);
            out[t] = (float)c * invP;
        }
        if (tid == 0) g_ticket = 0;            // reset for next graph replay
    }
}

extern "C" void kernel_launch(void* const* d_in, const int* in_sizes, int n_in,
                              void* d_out, int out_size) {
    const float* x4  = (const float*)d_in[0];
    const float* x8  = (const float*)d_in[1];
    const float* x16 = (const float*)d_in[2];
    float* out = (float*)d_out;

    perc_kernel<<<NCHUNK, 256>>>(x4, x8, x16, out);
}

// round 9
// speedup vs baseline: 1.1976x; 1.1976x over previous
#include <cuda_runtime.h>

// PercolationQ: per-patch occupancy fraction -> threshold -> mean over patches.
// Pure HBM-bound streaming reduction over three 50 MB fp32 tensors.
//
//   x4 : [3,64,4096,4,4]   patch = 16 floats  (4 lanes)
//   x8 : [3,64,1024,8,8]   patch = 64 floats  (16 lanes)
//   x16: [3,64, 256,16,16] patch = 256 floats (2 warp-iterations)
// Output: [q4(3,64), q8(3,64), q16(3,64)] = 576 floats.
//
// R8: warp-granular, barrier-free streaming in EXACTLY one wave.
//   grid = 1184 blocks x 256 threads, __launch_bounds__(256,8) caps regs at 32
//   -> all 9472 warps co-resident (148 SMs x 8 blocks). Work unit = one 16 KB
//   segment per warp (9216 segments total); each warp streams its segment with
//   coalesced LDG.128 (512 B per warp-load), reduces patches via shfl, and does
//   ONE integer atomicAdd into its row counter (order-independent => exactly
//   deterministic). No __syncthreads during streaming. Last block (ticket)
//   finalizes: out[row] = cnt * invP, then resets counters for graph replay.

#define PERC_THR 0.59275f
#define NBLK 1184
#define NSEG 9216              // 16 KB segments: 3*50.3MB / 16KB

__device__ int g_cnt[576];              // per-row patch counts (int -> exact)
__device__ unsigned int g_ticket = 0;   // self-resetting -> deterministic replays

__device__ __forceinline__ float red4(float4 a) {
    return (a.x + a.y) + (a.z + a.w);
}

__global__ void __launch_bounds__(256, 8)
perc_kernel(const float* __restrict__ x4,
            const float* __restrict__ x8,
            const float* __restrict__ x16,
            float* __restrict__ out) {
    __shared__ bool sh_last;

    const int tid  = threadIdx.x;
    const int lane = tid & 31;
    const int seg  = blockIdx.x * 8 + (tid >> 5);   // global warp id = segment id

    if (seg < NSEG) {
        // Segment -> tensor + base. 16 KB = 1024 float4. Rows are 256 KB = 16 segs;
        // seg>>4 gives the global row id 0..575 (boundaries align: 3072>>4=192).
        const float4* p;
        int tcase;
        if (seg < 3072)      { p = (const float4*)x4  + (size_t)seg * 1024;          tcase = 0; }
        else if (seg < 6144) { p = (const float4*)x8  + (size_t)(seg - 3072) * 1024; tcase = 1; }
        else                 { p = (const float4*)x16 + (size_t)(seg - 6144) * 1024; tcase = 2; }

        int cnt = 0;
        if (tcase == 0) {
            // x4: patch = 4 lanes; 8 patches per warp-iteration
#pragma unroll
            for (int i = 0; i < 32; i += 4) {
                float4 v0 = p[(i + 0) * 32 + lane];
                float4 v1 = p[(i + 1) * 32 + lane];
                float4 v2 = p[(i + 2) * 32 + lane];
                float4 v3 = p[(i + 3) * 32 + lane];
                float a0 = red4(v0), a1 = red4(v1), a2 = red4(v2), a3 = red4(v3);
                a0 += __shfl_xor_sync(0xffffffffu, a0, 1);
                a1 += __shfl_xor_sync(0xffffffffu, a1, 1);
                a2 += __shfl_xor_sync(0xffffffffu, a2, 1);
                a3 += __shfl_xor_sync(0xffffffffu, a3, 1);
                a0 += __shfl_xor_sync(0xffffffffu, a0, 2);
                a1 += __shfl_xor_sync(0xffffffffu, a1, 2);
                a2 += __shfl_xor_sync(0xffffffffu, a2, 2);
                a3 += __shfl_xor_sync(0xffffffffu, a3, 2);
                if ((lane & 3) == 0) {
                    cnt += (a0 * 0.0625f >= PERC_THR) ? 1 : 0;
                    cnt += (a1 * 0.0625f >= PERC_THR) ? 1 : 0;
                    cnt += (a2 * 0.0625f >= PERC_THR) ? 1 : 0;
                    cnt += (a3 * 0.0625f >= PERC_THR) ? 1 : 0;
                }
            }
        } else if (tcase == 1) {
            // x8: patch = 16 lanes; 2 patches per warp-iteration
#pragma unroll
            for (int i = 0; i < 32; i += 4) {
                float4 v0 = p[(i + 0) * 32 + lane];
                float4 v1 = p[(i + 1) * 32 + lane];
                float4 v2 = p[(i + 2) * 32 + lane];
                float4 v3 = p[(i + 3) * 32 + lane];
                float a0 = red4(v0), a1 = red4(v1), a2 = red4(v2), a3 = red4(v3);
#pragma unroll
                for (int m = 1; m <= 8; m <<= 1) {
                    a0 += __shfl_xor_sync(0xffffffffu, a0, m);
                    a1 += __shfl_xor_sync(0xffffffffu, a1, m);
                    a2 += __shfl_xor_sync(0xffffffffu, a2, m);
                    a3 += __shfl_xor_sync(0xffffffffu, a3, m);
                }
                if ((lane & 15) == 0) {
                    cnt += (a0 * 0.015625f >= PERC_THR) ? 1 : 0;
                    cnt += (a1 * 0.015625f >= PERC_THR) ? 1 : 0;
                    cnt += (a2 * 0.015625f >= PERC_THR) ? 1 : 0;
                    cnt += (a3 * 0.015625f >= PERC_THR) ? 1 : 0;
                }
            }
        } else {
            // x16: patch = 2 full warp-iterations; 2 patches per 4-load batch
#pragma unroll
            for (int i = 0; i < 32; i += 4) {
                float4 v0 = p[(i + 0) * 32 + lane];
                float4 v1 = p[(i + 1) * 32 + lane];
                float4 v2 = p[(i + 2) * 32 + lane];
                float4 v3 = p[(i + 3) * 32 + lane];
                float a = red4(v0) + red4(v1);
                float b = red4(v2) + red4(v3);
#pragma unroll
                for (int m = 1; m <= 16; m <<= 1) {
                    a += __shfl_xor_sync(0xffffffffu, a, m);
                    b += __shfl_xor_sync(0xffffffffu, b, m);
                }
                if (lane == 0) {
                    cnt += (a * 0.00390625f >= PERC_THR) ? 1 : 0;
                    cnt += (b * 0.00390625f >= PERC_THR) ? 1 : 0;
                }
            }
        }

        // Warp total -> one integer atomic per warp (order-independent, exact)
        cnt = __reduce_add_sync(0xffffffffu, cnt);
        if (lane == 0) atomicAdd(&g_cnt[seg >> 4], cnt);
    }

    // ---- last-block finalize (threadfence-reduction ticket pattern) ----
    __syncthreads();
    if (tid == 0) {
        __threadfence();                       // publish this block's atomics
        unsigned int t = atomicAdd(&g_ticket, 1);
        sh_last = (t == NBLK - 1);
    }
    __syncthreads();
    if (sh_last) {
        for (int t = tid; t < 576; t += 256) {
            int c = g_cnt[t];
            const float invP = (t < 192) ? (1.0f / 4096.0f)
                             : (t < 384) ? (1.0f / 1024.0f)
                                         : (1.0f / 256.0f);
            out[t] = (float)c * invP;
            g_cnt[t] = 0;                      // reset for next graph replay
        }
        if (tid == 0) g_ticket = 0;
    }
}

extern "C" void kernel_launch(void* const* d_in, const int* in_sizes, int n_in,
                              void* d_out, int out_size) {
    const float* x4  = (const float*)d_in[0];
    const float* x8  = (const float*)d_in[1];
    const float* x16 = (const float*)d_in[2];
    float* out = (float*)d_out;

    perc_kernel<<<NBLK, 256>>>(x4, x8, x16, out);
}

// round 10
// speedup vs baseline: 1.2149x; 1.0145x over previous
#include <cuda_runtime.h>

// PercolationQ: per-patch occupancy fraction -> threshold -> mean over patches.
// Pure HBM-bound streaming reduction over three 50 MB fp32 tensors.
//
//   x4 : [3,64,4096,4,4]   patch = 16 floats  (4 lanes)
//   x8 : [3,64,1024,8,8]   patch = 64 floats  (16 lanes)
//   x16: [3,64, 256,16,16] patch = 256 floats (2 warp-iterations)
// Output: [q4(3,64), q8(3,64), q16(3,64)] = 576 floats.
//
// R9: mode-W persistent grid -- ONE CTA per SM (148 blocks x 1024 threads,
// 32 warps/SM). Eliminates cross-CTA L1tex-queue contention / completion
// spread (the B300 model's mode-A 1.9x vs mode-W 1.003x), which is the one
// mechanism consistent with five designs all plateauing at ~5.4 TB/s with
// DRAM only ~68% busy. Each warp grid-strides over 16 KB segments with
// 8 LDG.128 in flight (4 KB/warp; 128 KB/SM >> latency-BW product).
// Integer per-warp atomicAdd per segment (order-independent => exact),
// last-block ticket finalize, self-resetting for graph replays.

#define PERC_THR 0.59275f
#define NBLK 148
#define NTHR 1024
#define NWARP (NBLK * 32)      // 4736 warps
#define NSEG 9216              // 16 KB segments: 3 * 50.3 MB / 16 KB

__device__ int g_cnt[576];              // per-row patch counts (int -> exact)
__device__ unsigned int g_ticket = 0;   // self-resetting -> deterministic replays

__device__ __forceinline__ float red4(float4 a) {
    return (a.x + a.y) + (a.z + a.w);
}

__global__ void __launch_bounds__(NTHR, 1)
perc_kernel(const float* __restrict__ x4,
            const float* __restrict__ x8,
            const float* __restrict__ x16,
            float* __restrict__ out) {
    __shared__ bool sh_last;

    const int tid   = threadIdx.x;
    const int lane  = tid & 31;
    const int gwarp = blockIdx.x * 32 + (tid >> 5);

    for (int seg = gwarp; seg < NSEG; seg += NWARP) {
        // Segment -> tensor + base. 16 KB = 1024 float4. Row = 256 KB = 16 segs;
        // seg>>4 is the global row id 0..575 (tensor boundaries align).
        const float4* p;
        int tcase;
        if (seg < 3072)      { p = (const float4*)x4  + (size_t)seg * 1024;          tcase = 0; }
        else if (seg < 6144) { p = (const float4*)x8  + (size_t)(seg - 3072) * 1024; tcase = 1; }
        else                 { p = (const float4*)x16 + (size_t)(seg - 6144) * 1024; tcase = 2; }

        int cnt = 0;
#pragma unroll 1
        for (int i = 0; i < 32; i += 8) {
            // 8 coalesced warp-loads in flight (4 KB per warp)
            float4 v[8];
#pragma unroll
            for (int j = 0; j < 8; j++)
                v[j] = p[(i + j) * 32 + lane];

            float a[8];
#pragma unroll
            for (int j = 0; j < 8; j++)
                a[j] = red4(v[j]);

            if (tcase == 0) {
                // x4: patch = 4 lanes
#pragma unroll
                for (int j = 0; j < 8; j++) {
                    a[j] += __shfl_xor_sync(0xffffffffu, a[j], 1);
                    a[j] += __shfl_xor_sync(0xffffffffu, a[j], 2);
                }
                if ((lane & 3) == 0) {
#pragma unroll
                    for (int j = 0; j < 8; j++)
                        cnt += (a[j] * 0.0625f >= PERC_THR) ? 1 : 0;
                }
            } else if (tcase == 1) {
                // x8: patch = 16 lanes
#pragma unroll
                for (int j = 0; j < 8; j++) {
#pragma unroll
                    for (int m = 1; m <= 8; m <<= 1)
                        a[j] += __shfl_xor_sync(0xffffffffu, a[j], m);
                }
                if ((lane & 15) == 0) {
#pragma unroll
                    for (int j = 0; j < 8; j++)
                        cnt += (a[j] * 0.015625f >= PERC_THR) ? 1 : 0;
                }
            } else {
                // x16: patch = 2 consecutive warp-iterations -> 4 patches/batch
                float b[4];
#pragma unroll
                for (int j = 0; j < 4; j++)
                    b[j] = a[2 * j] + a[2 * j + 1];
#pragma unroll
                for (int j = 0; j < 4; j++) {
#pragma unroll
                    for (int m = 1; m <= 16; m <<= 1)
                        b[j] += __shfl_xor_sync(0xffffffffu, b[j], m);
                }
                if (lane == 0) {
#pragma unroll
                    for (int j = 0; j < 4; j++)
                        cnt += (b[j] * 0.00390625f >= PERC_THR) ? 1 : 0;
                }
            }
        }

        // Warp total -> one integer atomic per segment (order-independent, exact)
        cnt = __reduce_add_sync(0xffffffffu, cnt);
        if (lane == 0) atomicAdd(&g_cnt[seg >> 4], cnt);
    }

    // ---- last-block finalize (threadfence-reduction ticket pattern) ----
    __syncthreads();
    if (tid == 0) {
        __threadfence();                       // publish this block's atomics
        unsigned int t = atomicAdd(&g_ticket, 1);
        sh_last = (t == NBLK - 1);
    }
    __syncthreads();
    if (sh_last) {
        for (int t = tid; t < 576; t += NTHR) {
            int c = g_cnt[t];
            const float invP = (t < 192) ? (1.0f / 4096.0f)
                             : (t < 384) ? (1.0f / 1024.0f)
                                         : (1.0f / 256.0f);
            out[t] = (float)c * invP;
            g_cnt[t] = 0;                      // reset for next graph replay
        }
        if (tid == 0) g_ticket = 0;
    }
}

extern "C" void kernel_launch(void* const* d_in, const int* in_sizes, int n_in,
                              void* d_out, int out_size) {
    const float* x4  = (const float*)d_in[0];
    const float* x8  = (const float*)d_in[1];
    const float* x16 = (const float*)d_in[2];
    float* out = (float*)d_out;

    perc_kernel<<<NBLK, NTHR>>>(x4, x8, x16, out);
}